// round 7
// baseline (speedup 1.0000x reference)
#include <cuda_runtime.h>
#include <cstdint>

#define SLEN   53
#define NPIX   (SLEN * SLEN)     // 2809
#define TPB    256
#define NMAIN  (SLEN * 13)       // 689 four-row units (rows 0..51)
#define GRID   1184              // 148 SMs x 8 resident CTAs: single wave

__device__ __forceinline__ float frcp_(float x){ float r; asm("rcp.approx.ftz.f32 %0, %1;" : "=f"(r) : "f"(x)); return r; }
__device__ __forceinline__ float flg2_(float x){ float r; asm("lg2.approx.ftz.f32 %0, %1;" : "=f"(r) : "f"(x)); return r; }
__device__ __forceinline__ float frsq_(float x){ float r; asm("rsqrt.approx.ftz.f32 %0, %1;" : "=f"(r) : "f"(x)); return r; }

// Cephes-style atan, single MUFU rcp. Max err ~3e-7.
__device__ __forceinline__ float fast_atan(float v) {
    float a  = fabsf(v);
    bool  c1 = a > 2.414213562f;
    bool  c2 = a > 0.414213562f;
    float num = c1 ? -1.0f : (a - 1.0f);
    float den = c1 ?  a    : (a + 1.0f);
    float xr  = num * frcp_(den);
    float x   = c2 ? xr : a;
    float y0  = c1 ? 1.57079632679f : (c2 ? 0.78539816339f : 0.0f);
    float z = x * x;
    float p = fmaf(8.05374449538e-2f, z, -1.38776856032e-1f);
    p = fmaf(p, z, 1.99777106478e-1f);
    p = fmaf(p, z, -3.33329491539e-1f);
    float y = fmaf(p * z, x, x) + y0;
    return copysignf(y, v);
}

// smem scalar slots
#define S_Q     0
#define S_INVQ  1
#define S_QF    2
#define S_BSAFE 3
#define S_KLOG  4
#define S_COSP  5
#define S_SINP  6
#define S_CX26  7
#define S_CY26  8

__global__ void __launch_bounds__(TPB)
lens_decoder_kernel(const float* __restrict__ params,   // [ntiles, 12]
                    const float* __restrict__ bools,    // [ntiles]
                    float* __restrict__ out,            // [ntiles, NPIX]
                    int ntiles)
{
    __shared__ float  sc[12];
    __shared__ float2 etab[SLEN + 1];   // zero sentinels at [0] and [53]

    const int tid = threadIdx.x;

    for (int tile = blockIdx.x; tile < ntiles; tile += GRID) {
        float* o = out + (size_t)tile * NPIX;

        // ---- zero-tile fast path (~30%): vectorized exact-0 fill ----
        if (bools[tile] == 0.0f) {            // uniform across block
            const int phase = (int)(((unsigned long long)o >> 2) & 3ull);
            const int head  = (4 - phase) & 3;
            if (tid < head) o[tid] = 0.0f;
            float4* ov = (float4*)(o + head);
            const int nvec = (NPIX - head) >> 2;
            for (int p = tid; p < nvec; p += TPB)
                ov[p] = make_float4(0.0f, 0.0f, 0.0f, 0.0f);
            const int done = head + (nvec << 2);
            if (done + tid < NPIX) o[done + tid] = 0.0f;
            continue;
        }

        // protect smem reuse across tile iterations (uniform branch -> safe)
        __syncthreads();

        // ---- parallel preamble ----
        // warps 0-1 (tids 0..53): build delta table directly (2 expf each)
        if (tid <= SLEN) {
            if (tid == 0 || tid == SLEN) {
                etab[tid] = make_float2(0.0f, 0.0f);
            } else {
                const float* pr = params + tile * 12;
                const float flux  = fmaf(pr[0], 1000.0f, 100.0f);
                const float sigma = fmaf(pr[3], 3.0f, 1.0f);
                const float s2    = sigma * sigma;
                const float sAm   = sqrtf(flux / (6.283185307179586f * s2));
                const float n2s2  = -0.5f / s2;
                const float d0 = (float)(tid - 1) - 26.0f;
                const float d1 = (float)tid - 26.0f;
                const float e0 = sAm * expf(n2s2 * d0 * d0);
                const float e1 = sAm * expf(n2s2 * d1 * d1);
                etab[tid] = make_float2(e0, e1 - e0);
            }
        }
        // warp 2, one lane: rotation/deflection scalars (runs concurrently)
        if (tid == 64) {
            const float* pr = params + tile * 12;
            const float b   = pr[7];
            const float e1p = pr[10];
            const float e2p = pr[11];
            const float ell = sqrtf(e1p * e1p + e2p * e2p);
            const float q   = (1.0f - ell) / (1.0f + ell);
            const float phir = atanf(e2p / e1p);
            float sinp, cosp;
            sincosf(phir, &sinp, &cosp);
            const float invq  = 1.0f / q;
            // data guarantees q in [0.1,0.9] -> qfact >= 0.459 >> eps (fallback dead)
            const float qfact = sqrtf(invq - q);
            const float bsafe = b / qfact;
            sc[S_Q]     = q;
            sc[S_INVQ]  = invq;
            sc[S_QF]    = qfact;
            sc[S_BSAFE] = bsafe;
            sc[S_KLOG]  = bsafe * 0.34657359028f;   // bsafe * 0.5 * ln2
            sc[S_COSP]  = cosp;
            sc[S_SINP]  = sinp;
            sc[S_CX26]  = pr[8] + 26.0f;
            sc[S_CY26]  = pr[9] + 26.0f;
        }
        __syncthreads();

        const float q     = sc[S_Q];
        const float invq  = sc[S_INVQ];
        const float qfact = sc[S_QF];
        const float bsafe = sc[S_BSAFE];
        const float klog  = sc[S_KLOG];
        const float cosp  = sc[S_COSP];
        const float sinp  = sc[S_SINP];
        const float cx26  = sc[S_CX26];
        const float cy26  = sc[S_CY26];

        const float scale = 53.0f / 52.0f;
        const float dxs_y = scale * sinp;
        const float dys_y = scale * cosp;
        const float2* etp = &etab[1];          // bias folded into base

        auto pixel = [&](float xsie, float ysie, float xc, float yc) -> float {
            const float t     = fmaf(q * xsie, xsie, fmaf(invq * ysie, ysie, 1e-12f));
            const float srinv = qfact * frsq_(t);
            const float zx = xsie * srinv;
            const float zy = ysie * srinv;            // |zy| <= 0.995

            const float xtg = bsafe * fast_atan(zx);
            const float ratio = (1.0f + zy) * frcp_(1.0f - zy);
            const float ytg = klog * flg2_(ratio);    // bsafe * atanh(zy)

            const float xs = fmaf(-xtg, cosp, fmaf( ytg, sinp, xc));
            const float ys = fmaf(-ytg, cosp, fmaf(-xtg, sinp, yc));

            const float fx = floorf(xs);
            const float fy = floorf(ys);
            const float ffx = xs - fx;
            const float ffy = ys - fy;
            const int idx = (int)fminf(fmaxf(fx, -1.0f), 52.0f);  // [-1,52]
            const int idy = (int)fminf(fmaxf(fy, -1.0f), 52.0f);

            const float2 exd = etp[idx];
            const float2 eyd = etp[idy];
            const float wx = fmaf(ffx, exd.y, exd.x);
            const float wy = fmaf(ffy, eyd.y, eyd.x);
            return wx * wy;
        };

        // ---- main: 689 four-row units (rows 0..51) ----
        for (int u = tid; u < NMAIN; u += TPB) {
            const int strip = (u * 1237) >> 16;        // == u/53 for u < 742
            const int j     = u - strip * 53;
            const int i0    = strip * 4;

            const float xc  = fmaf((float)j,  scale, -1.0f);
            const float yc0 = fmaf((float)i0, scale, -1.0f);
            const float dx  = xc  - cx26;
            const float dy0 = yc0 - cy26;

            float xsie = fmaf(dx,  cosp,  dy0 * sinp);
            float ysie = fmaf(dy0, cosp, -dx  * sinp);
            float yc   = yc0;

            float* ocol = o + i0 * SLEN + j;

            #pragma unroll
            for (int k = 0; k < 4; k++) {
                ocol[k * SLEN] = pixel(xsie, ysie, xc, yc);
                xsie += dxs_y;
                ysie += dys_y;
                yc   += scale;
            }
        }

        // ---- tail: row 52 ----
        if (tid < SLEN) {
            const float xc = fmaf((float)tid, scale, -1.0f);
            const float yc = fmaf(52.0f, scale, -1.0f);
            const float dx = xc - cx26;
            const float dy = yc - cy26;
            const float xsie = fmaf(dx, cosp,  dy * sinp);
            const float ysie = fmaf(dy, cosp, -dx * sinp);
            o[52 * SLEN + tid] = pixel(xsie, ysie, xc, yc);
        }
    }
}

extern "C" void kernel_launch(void* const* d_in, const int* in_sizes, int n_in,
                              void* d_out, int out_size)
{
    const float* params = (const float*)d_in[0];   // lens_params  [4096,1,12]
    const float* bmask  = (const float*)d_in[1];   // bools        [4096,1,1]
    float* out = (float*)d_out;

    const int ntiles = out_size / NPIX;            // 4096
    lens_decoder_kernel<<<GRID, TPB>>>(params, bmask, out, ntiles);
}

// round 8
// speedup vs baseline: 1.8081x; 1.8081x over previous
#include <cuda_runtime.h>
#include <cstdint>

#define SLEN   53
#define NPIX   (SLEN * SLEN)     // 2809
#define TPB    256
#define NUNITS (SLEN * 14)       // 742 strip units; strip 13 = row 52 only

__device__ __forceinline__ float frcp_(float x){ float r; asm("rcp.approx.ftz.f32 %0, %1;" : "=f"(r) : "f"(x)); return r; }
__device__ __forceinline__ float flg2_(float x){ float r; asm("lg2.approx.ftz.f32 %0, %1;" : "=f"(r) : "f"(x)); return r; }
__device__ __forceinline__ float frsq_(float x){ float r; asm("rsqrt.approx.ftz.f32 %0, %1;" : "=f"(r) : "f"(x)); return r; }

// Cephes-style atan, single MUFU rcp. Max err ~3e-7.
__device__ __forceinline__ float fast_atan(float v) {
    float a  = fabsf(v);
    bool  c1 = a > 2.414213562f;
    bool  c2 = a > 0.414213562f;
    float num = c1 ? -1.0f : (a - 1.0f);
    float den = c1 ?  a    : (a + 1.0f);
    float xr  = num * frcp_(den);
    float x   = c2 ? xr : a;
    float y0  = c1 ? 1.57079632679f : (c2 ? 0.78539816339f : 0.0f);
    float z = x * x;
    float p = fmaf(8.05374449538e-2f, z, -1.38776856032e-1f);
    p = fmaf(p, z, 1.99777106478e-1f);
    p = fmaf(p, z, -3.33329491539e-1f);
    float y = fmaf(p * z, x, x) + y0;
    return copysignf(y, v);
}

// smem scalar slots
#define S_Q     0
#define S_INVQ  1
#define S_QF    2
#define S_BCA   3   // bsafe * cosp
#define S_BSA   4   // bsafe * sinp
#define S_BCL   5   // bsafe * cosp * 0.5*ln2
#define S_BSL   6   // bsafe * sinp * 0.5*ln2
#define S_CX26  7
#define S_CY26  8

__global__ void __launch_bounds__(TPB)
lens_decoder_kernel(const float* __restrict__ params,   // [ntiles, 12]
                    const float* __restrict__ bools,    // [ntiles]
                    float* __restrict__ out)            // [ntiles, NPIX]
{
    __shared__ float  sc[12];
    __shared__ float2 etab[SLEN + 1];   // zero sentinels at [0] and [53]

    const int tid  = threadIdx.x;
    const int tile = blockIdx.x;
    float* o = out + (size_t)tile * NPIX;

    // ---- zero-tile fast path (~30%): vectorized exact-0 fill ----
    if (bools[tile] == 0.0f) {
        const int phase = (int)(((unsigned long long)o >> 2) & 3ull);
        const int head  = (4 - phase) & 3;
        if (tid < head) o[tid] = 0.0f;
        float4* ov = (float4*)(o + head);
        const int nvec = (NPIX - head) >> 2;
        for (int p = tid; p < nvec; p += TPB)
            ov[p] = make_float4(0.0f, 0.0f, 0.0f, 0.0f);
        const int done = head + (nvec << 2);
        if (done + tid < NPIX) o[done + tid] = 0.0f;
        return;
    }

    // ---- parallel preamble (single sync) ----
    // warps 0-1 (tids 0..53): build delta table directly (2 expf each)
    if (tid <= SLEN) {
        if (tid == 0 || tid == SLEN) {
            etab[tid] = make_float2(0.0f, 0.0f);
        } else {
            const float* pr = params + tile * 12;
            const float flux  = fmaf(pr[0], 1000.0f, 100.0f);
            const float sigma = fmaf(pr[3], 3.0f, 1.0f);
            const float s2    = sigma * sigma;
            const float sAm   = sqrtf(flux / (6.283185307179586f * s2));
            const float n2s2  = -0.5f / s2;
            const float d0 = (float)(tid - 1) - 26.0f;
            const float d1 = (float)tid - 26.0f;
            const float e0 = sAm * expf(n2s2 * d0 * d0);
            const float e1 = sAm * expf(n2s2 * d1 * d1);
            etab[tid] = make_float2(e0, e1 - e0);
        }
    }
    // warp 2, one lane: rotation/deflection scalars (runs concurrently)
    if (tid == 64) {
        const float* pr = params + tile * 12;
        const float b   = pr[7];
        const float e1p = pr[10];
        const float e2p = pr[11];
        const float ell = sqrtf(e1p * e1p + e2p * e2p);
        const float q   = (1.0f - ell) / (1.0f + ell);
        const float phir = atanf(e2p / e1p);
        float sinp, cosp;
        sincosf(phir, &sinp, &cosp);
        const float invq  = 1.0f / q;
        // data guarantees q in [0.1,0.9] -> qfact >= 0.459 >> eps (fallback dead)
        const float qfact = sqrtf(invq - q);
        const float bsafe = b / qfact;
        const float bcA = bsafe * cosp;
        const float bsA = bsafe * sinp;
        sc[S_Q]    = q;
        sc[S_INVQ] = invq;
        sc[S_QF]   = qfact;
        sc[S_BCA]  = bcA;
        sc[S_BSA]  = bsA;
        sc[S_BCL]  = bcA * 0.34657359028f;   // * 0.5*ln2
        sc[S_BSL]  = bsA * 0.34657359028f;
        sc[S_CX26] = pr[8] + 26.0f;
        sc[S_CY26] = pr[9] + 26.0f;
        // sin/cos needed per-strip for SIE rotation: stash too
        sc[9]  = cosp;
        sc[10] = sinp;
    }
    __syncthreads();

    const float q     = sc[S_Q];
    const float invq  = sc[S_INVQ];
    const float qfact = sc[S_QF];
    const float bcA   = sc[S_BCA];
    const float bsA   = sc[S_BSA];
    const float bcL   = sc[S_BCL];
    const float bsL   = sc[S_BSL];
    const float cx26  = sc[S_CX26];
    const float cy26  = sc[S_CY26];
    const float cosp  = sc[9];
    const float sinp  = sc[10];

    const float scale = 53.0f / 52.0f;
    const float dxs_y = scale * sinp;
    const float dys_y = scale * cosp;
    const float2* etp = &etab[1];          // bias folded into base

    // per-pixel body
    auto pixel = [&](float xsie, float ysie, float xc, float yc) -> float {
        const float t     = fmaf(q * xsie, xsie, fmaf(invq * ysie, ysie, 1e-12f));
        const float srinv = qfact * frsq_(t);
        const float zx = xsie * srinv;
        const float zy = ysie * srinv;            // |zy| <= 0.995

        const float A = fast_atan(zx);
        const float L = flg2_((1.0f + zy) * frcp_(1.0f - zy));   // atanh = 0.5*ln2*L

        // xs = xc - bsafe*(A*cosp - H*sinp); ys = yc - bsafe*(H*cosp + A*sinp)
        const float xs = fmaf(-bcA, A, fmaf( bsL, L, xc));
        const float ys = fmaf(-bsA, A, fmaf(-bcL, L, yc));

        const float fx = floorf(xs);
        const float fy = floorf(ys);
        const float ffx = xs - fx;
        const float ffy = ys - fy;
        const int idx = (int)fminf(fmaxf(fx, -1.0f), 52.0f);  // [-1,52]
        const int idy = (int)fminf(fmaxf(fy, -1.0f), 52.0f);

        const float2 exd = etp[idx];
        const float2 eyd = etp[idy];
        const float wx = fmaf(ffx, exd.y, exd.x);
        const float wy = fmaf(ffy, eyd.y, eyd.x);
        return wx * wy;
    };

    // ---- main: 742 strip units; strips 0..12 full 4 rows, strip 13 = row 52 ----
    for (int u = tid; u < NUNITS; u += TPB) {
        const int strip = (u * 1237) >> 16;        // == u/53 for u < 742
        const int j     = u - strip * 53;
        const int i0    = strip * 4;

        const float xc  = fmaf((float)j,  scale, -1.0f);
        const float yc0 = fmaf((float)i0, scale, -1.0f);
        const float dx  = xc  - cx26;
        const float dy0 = yc0 - cy26;

        float xsie = fmaf(dx,  cosp,  dy0 * sinp);
        float ysie = fmaf(dy0, cosp, -dx  * sinp);
        float yc   = yc0;

        float* ocol = o + i0 * SLEN + j;

        #pragma unroll
        for (int k = 0; k < 4; k++) {
            if (i0 + k < SLEN)                      // strips 0..12: always true
                ocol[k * SLEN] = pixel(xsie, ysie, xc, yc);
            xsie += dxs_y;
            ysie += dys_y;
            yc   += scale;
        }
    }
}

extern "C" void kernel_launch(void* const* d_in, const int* in_sizes, int n_in,
                              void* d_out, int out_size)
{
    const float* params = (const float*)d_in[0];   // lens_params  [4096,1,12]
    const float* bmask  = (const float*)d_in[1];   // bools        [4096,1,1]
    float* out = (float*)d_out;

    const int ntiles = out_size / NPIX;            // 4096
    lens_decoder_kernel<<<ntiles, TPB>>>(params, bmask, out);
}

// round 9
// speedup vs baseline: 1.9889x; 1.1000x over previous
#include <cuda_runtime.h>
#include <cstdint>

#define SLEN   53
#define NPIX   (SLEN * SLEN)     // 2809
#define TPB    256
#define NUNITS (SLEN * 14)       // 742 strip units; strip 13 = row 52 only

// extended sentinel table: covers idx in [-225, 276]
#define TBIAS  225
#define TSIZE  502               // entries [0,501] <-> idx [-225,276]

__device__ __forceinline__ float frcp_(float x){ float r; asm("rcp.approx.ftz.f32 %0, %1;" : "=f"(r) : "f"(x)); return r; }
__device__ __forceinline__ float flg2_(float x){ float r; asm("lg2.approx.ftz.f32 %0, %1;" : "=f"(r) : "f"(x)); return r; }
__device__ __forceinline__ float frsq_(float x){ float r; asm("rsqrt.approx.ftz.f32 %0, %1;" : "=f"(r) : "f"(x)); return r; }

// Cephes-style atan, single MUFU rcp. Max err ~3e-7.
__device__ __forceinline__ float fast_atan(float v) {
    float a  = fabsf(v);
    bool  c1 = a > 2.414213562f;
    bool  c2 = a > 0.414213562f;
    float num = c1 ? -1.0f : (a - 1.0f);
    float den = c1 ?  a    : (a + 1.0f);
    float xr  = num * frcp_(den);
    float x   = c2 ? xr : a;
    float y0  = c1 ? 1.57079632679f : (c2 ? 0.78539816339f : 0.0f);
    float z = x * x;
    float p = fmaf(8.05374449538e-2f, z, -1.38776856032e-1f);
    p = fmaf(p, z, 1.99777106478e-1f);
    p = fmaf(p, z, -3.33329491539e-1f);
    float y = fmaf(p * z, x, x) + y0;
    return copysignf(y, v);
}

// smem scalar slots
#define S_Q     0
#define S_INVQ  1
#define S_QF    2
#define S_BCA   3   // bsafe * cosp
#define S_BSA   4   // bsafe * sinp
#define S_BCL   5   // bsafe * cosp * 0.5*ln2
#define S_BSL   6   // bsafe * sinp * 0.5*ln2
#define S_K1    7   // cx26*cosp + cy26*sinp
#define S_K2    8   // cy26*cosp - cx26*sinp
#define S_COSP  9
#define S_SINP  10

__global__ void __launch_bounds__(TPB)
lens_decoder_kernel(const float* __restrict__ params,   // [ntiles, 12]
                    const float* __restrict__ bools,    // [ntiles]
                    float* __restrict__ out)            // [ntiles, NPIX]
{
    __shared__ float  sc[12];
    __shared__ float2 etab[TSIZE];

    const int tid  = threadIdx.x;
    const int tile = blockIdx.x;
    float* o = out + (size_t)tile * NPIX;

    // ---- zero-tile fast path (~30%): vectorized exact-0 fill ----
    if (bools[tile] == 0.0f) {
        const int phase = (int)(((unsigned long long)o >> 2) & 3ull);
        const int head  = (4 - phase) & 3;
        if (tid < head) o[tid] = 0.0f;
        float4* ov = (float4*)(o + head);
        const int nvec = (NPIX - head) >> 2;
        for (int p = tid; p < nvec; p += TPB)
            ov[p] = make_float4(0.0f, 0.0f, 0.0f, 0.0f);
        const int done = head + (nvec << 2);
        if (done + tid < NPIX) o[done + tid] = 0.0f;
        return;
    }

    // ---- parallel preamble (single sync); disjoint writers ----
    // zero margins: entries [0,224] (idx -225..-1) and [278,501] (idx 53..276)
    if (tid < TBIAS)       etab[tid]       = make_float2(0.0f, 0.0f);
    if (tid < 224)         etab[278 + tid] = make_float2(0.0f, 0.0f);
    // real entries: idx k in [0,52] -> entry 225+k. k=52 is the zero edge row.
    if (tid <= 52) {
        if (tid == 52) {
            etab[TBIAS + 52] = make_float2(0.0f, 0.0f);
        } else {
            const float* pr = params + tile * 12;
            const float flux  = fmaf(pr[0], 1000.0f, 100.0f);
            const float sigma = fmaf(pr[3], 3.0f, 1.0f);
            const float s2    = sigma * sigma;
            const float sAm   = sqrtf(flux / (6.283185307179586f * s2));
            const float n2s2  = -0.5f / s2;
            const float d0 = (float)tid - 26.0f;
            const float d1 = (float)(tid + 1) - 26.0f;
            const float e0 = sAm * expf(n2s2 * d0 * d0);
            const float e1 = sAm * expf(n2s2 * d1 * d1);
            etab[TBIAS + tid] = make_float2(e0, e1 - e0);
        }
    }
    // warp 2, one lane: rotation/deflection scalars (runs concurrently)
    if (tid == 64) {
        const float* pr = params + tile * 12;
        const float b   = pr[7];
        const float cx26 = pr[8] + 26.0f;
        const float cy26 = pr[9] + 26.0f;
        const float e1p = pr[10];
        const float e2p = pr[11];
        const float ell = sqrtf(e1p * e1p + e2p * e2p);
        const float q   = (1.0f - ell) / (1.0f + ell);
        const float phir = atanf(e2p / e1p);
        float sinp, cosp;
        sincosf(phir, &sinp, &cosp);
        const float invq  = 1.0f / q;
        // data guarantees q in [0.1,0.9] -> qfact >= 0.459 >> eps (fallback dead)
        const float qfact = sqrtf(invq - q);
        const float bsafe = b / qfact;
        const float bcA = bsafe * cosp;
        const float bsA = bsafe * sinp;
        sc[S_Q]    = q;
        sc[S_INVQ] = invq;
        sc[S_QF]   = qfact;
        sc[S_BCA]  = bcA;
        sc[S_BSA]  = bsA;
        sc[S_BCL]  = bcA * 0.34657359028f;   // * 0.5*ln2
        sc[S_BSL]  = bsA * 0.34657359028f;
        sc[S_K1]   = fmaf(cx26, cosp,  cy26 * sinp);
        sc[S_K2]   = fmaf(cy26, cosp, -cx26 * sinp);
        sc[S_COSP] = cosp;
        sc[S_SINP] = sinp;
    }
    __syncthreads();

    const float q     = sc[S_Q];
    const float invq  = sc[S_INVQ];
    const float qfact = sc[S_QF];
    const float bcA   = sc[S_BCA];
    const float bsA   = sc[S_BSA];
    const float bcL   = sc[S_BCL];
    const float bsL   = sc[S_BSL];
    const float K1    = sc[S_K1];
    const float K2    = sc[S_K2];
    const float cosp  = sc[S_COSP];
    const float sinp  = sc[S_SINP];

    const float scale = 53.0f / 52.0f;
    const float dxs_y = scale * sinp;
    const float dys_y = scale * cosp;
    const float2* etp = &etab[TBIAS];      // bias folded into base

    // per-pixel body (no clamps: table covers the full reachable index range)
    auto pixel = [&](float xsie, float ysie, float xc, float yc) -> float {
        const float t     = fmaf(q * xsie, xsie, fmaf(invq * ysie, ysie, 1e-12f));
        const float srinv = qfact * frsq_(t);
        const float zx = xsie * srinv;
        const float zy = ysie * srinv;            // |zy| <= 0.995

        const float A = fast_atan(zx);
        const float L = flg2_((1.0f + zy) * frcp_(1.0f - zy));   // atanh = 0.5*ln2*L

        const float xs = fmaf(-bcA, A, fmaf( bsL, L, xc));
        const float ys = fmaf(-bsA, A, fmaf(-bcL, L, yc));

        const int ix = __float2int_rd(xs);        // floor, in [-222, 274]
        const int iy = __float2int_rd(ys);
        const float ffx = xs - (float)ix;
        const float ffy = ys - (float)iy;

        const float2 exd = etp[ix];
        const float2 eyd = etp[iy];
        const float wx = fmaf(ffx, exd.y, exd.x);
        const float wy = fmaf(ffy, eyd.y, eyd.x);
        return wx * wy;
    };

    // ---- main: 742 strip units; strips 0..12 full 4 rows, strip 13 = row 52 ----
    for (int u = tid; u < NUNITS; u += TPB) {
        const int strip = (u * 1237) >> 16;        // == u/53 for u < 742
        const int j     = u - strip * 53;
        const bool full = strip < 13;              // one bounds check per unit

        const float xc  = fmaf((float)j,     scale,       -1.0f);  // x + 26
        const float yc0 = fmaf((float)strip, 4.0f * scale, -1.0f); // y + 26

        float xsie = fmaf(yc0, sinp, fmaf(xc, cosp, -K1));
        float ysie = fmaf(yc0, cosp, -fmaf(xc, sinp, K2));
        float yc   = yc0;

        float* ocol = o + strip * (4 * SLEN) + j;

        // k = 0 always valid
        ocol[0] = pixel(xsie, ysie, xc, yc);
        #pragma unroll
        for (int k = 1; k < 4; k++) {
            xsie += dxs_y;
            ysie += dys_y;
            yc   += scale;
            if (full)
                ocol[k * SLEN] = pixel(xsie, ysie, xc, yc);
        }
    }
}

extern "C" void kernel_launch(void* const* d_in, const int* in_sizes, int n_in,
                              void* d_out, int out_size)
{
    const float* params = (const float*)d_in[0];   // lens_params  [4096,1,12]
    const float* bmask  = (const float*)d_in[1];   // bools        [4096,1,1]
    float* out = (float*)d_out;

    const int ntiles = out_size / NPIX;            // 4096
    lens_decoder_kernel<<<ntiles, TPB>>>(params, bmask, out);
}